// round 16
// baseline (speedup 1.0000x reference)
#include <cuda_runtime.h>
#include <cuda_fp16.h>

#define V_N   100000
#define E_N   1600000
#define NI    128
#define H     50
#define PW    52          // padded fp32 row width for g_acc / staged weights
#define LRW   32          // g_left/g_right fp16 row: 32 uints = 64 halfs = 128B
#define EFWH  54          // s_efh stride in halfs (27 uints, odd banks -> conflict-free)
#define XW    51          // X stride in uints (odd -> conflict-free)
#define EB    512         // edges per tile
#define NTE   512         // k_edge threads
#define NT    256         // node kernel threads

// ---- k_edge smem float-index layout ---------------------------------------
#define SM_EFH_F   0                      // s_efh: 512*54 halfs = 13824 floats
#define SM_X_F     13824                  // X: 512*51 uints = 26112 floats
#define SM_W2N_F   (13824 + 26112)        // 39936: 50x52 fp32
#define SM_W2E_F   (SM_W2N_F + 2600)      // 42536
#define SM_WU_F    (SM_W2E_F + 2600)      // 45136: 152x52 fp32
#define SM_B2N_F   (SM_WU_F + 7904)       // 53040
#define SM_B2E_F   (SM_B2N_F + 52)
#define SM_BU_F    (SM_B2E_F + 52)
#define SM_SRC_F   (SM_BU_F + 52)         // 512 ints
#define SM_DST_F   (SM_SRC_F + 512)
#define SM_EDGE_F  (SM_DST_F + 512)       // 54220 floats = 216880 bytes

typedef unsigned long long u64;

__device__ unsigned int g_leftH [(size_t)V_N * LRW];   // fp16x2 packed
__device__ unsigned int g_rightH[(size_t)V_N * LRW];   // fp16x2 packed
__device__ float        g_acc   [(size_t)V_N * PW];    // fp32 scatter accumulator

// ---- helpers --------------------------------------------------------------
__device__ __forceinline__ u64 pk2(float x, float y) {
    u64 r; asm("mov.b64 %0, {%1, %2};" : "=l"(r) : "f"(x), "f"(y)); return r;
}
__device__ __forceinline__ float2 up2(u64 v) {
    float2 r; asm("mov.b64 {%0, %1}, %2;" : "=f"(r.x), "=f"(r.y) : "l"(v)); return r;
}
__device__ __forceinline__ u64 ffma2(u64 a, u64 b, u64 c) {
    u64 d; asm("fma.rn.f32x2 %0, %1, %2, %3;" : "=l"(d) : "l"(a), "l"(b), "l"(c)); return d;
}
__device__ __forceinline__ float relu_f(float x) { return fmaxf(x, 0.0f); }
__device__ __forceinline__ __half2 u2h(unsigned int u) {
    union { unsigned int u; __half2 h; } c; c.u = u; return c.h;
}
__device__ __forceinline__ unsigned int h2u(__half2 h) {
    union { unsigned int u; __half2 h; } c; c.h = h; return c.u;
}
// relu(a+b) on packed fp16 pairs
__device__ __forceinline__ unsigned int hcomb(unsigned int a, unsigned int b) {
    return h2u(__hmax2(__hadd2(u2h(a), u2h(b)), __float2half2_rn(0.0f)));
}

__device__ __forceinline__ void red4(float* p, float a, float b, float c, float d) {
    asm volatile("red.global.add.v4.f32 [%0], {%1,%2,%3,%4};"
                 :: "l"(p), "f"(a), "f"(b), "f"(c), "f"(d) : "memory");
}

template <int Q>
__device__ __forceinline__ void acc1(u64* a, float x, const float* Wrow) {
    u64 xx = pk2(x, x);
    const ulonglong2* w = reinterpret_cast<const ulonglong2*>(Wrow);
    #pragma unroll
    for (int q = 0; q < Q; q++) {
        ulonglong2 ww = w[q];
        a[2 * q]     = ffma2(xx, ww.x, a[2 * q]);
        a[2 * q + 1] = ffma2(xx, ww.y, a[2 * q + 1]);
    }
}
template <int Q>
__device__ __forceinline__ void acc2(u64* a0, u64* a1, float x0, float x1,
                                     const float* Wrow) {
    u64 xx0 = pk2(x0, x0), xx1 = pk2(x1, x1);
    const ulonglong2* w = reinterpret_cast<const ulonglong2*>(Wrow);
    #pragma unroll
    for (int q = 0; q < Q; q++) {
        ulonglong2 ww = w[q];
        a0[2 * q]     = ffma2(xx0, ww.x, a0[2 * q]);
        a0[2 * q + 1] = ffma2(xx0, ww.y, a0[2 * q + 1]);
        a1[2 * q]     = ffma2(xx1, ww.x, a1[2 * q]);
        a1[2 * q + 1] = ffma2(xx1, ww.y, a1[2 * q + 1]);
    }
}
// 2-edge GEMM over column strip of width 2Q, fp16 inputs from smem
template <int Q>
__device__ __forceinline__ void gemm2h(const __half* f0, const __half* f1,
                                       const float* W, const float* B,
                                       u64* a0, u64* a1) {
    const u64* B2 = reinterpret_cast<const u64*>(B);
    #pragma unroll
    for (int q = 0; q < 2 * Q; q++) { a0[q] = B2[q]; a1[q] = B2[q]; }
    #pragma unroll 2
    for (int i = 0; i < H; i++)
        acc2<Q>(a0, a1, __half2float(f0[i]), __half2float(f1[i]), W + i * PW);
}

// Phase-3 fold for edge pair (e0,e1), column strip [co..): all inputs in smem.
// X rows: uints 0..24 = first (K-rows 0..49), 25..49 = second (K-rows 50..99).
// T (third, K-rows 100..149) read from s_efh as uints.
template <int Q, int QN>
__device__ __forceinline__ void fold2(
    const float* s_wu, const float* s_bu, int co,
    const unsigned int* X0, const unsigned int* X1,
    const unsigned int* T0u, const unsigned int* T1u,
    float* O0, float* O1)
{
    u64 o0[2 * Q], o1[2 * Q];
    const u64* B2 = reinterpret_cast<const u64*>(s_bu + co);
    #pragma unroll
    for (int q = 0; q < 2 * Q; q++) { o0[q] = B2[q]; o1[q] = B2[q]; }

    {   // first: w_u rows 0..49
        const float* W = s_wu + co;
        #pragma unroll 2
        for (int j = 0; j < 25; j++) {
            float2 v0 = __half22float2(u2h(X0[j]));
            float2 v1 = __half22float2(u2h(X1[j]));
            acc2<Q>(o0, o1, v0.x, v1.x, W + (2 * j) * PW);
            acc2<Q>(o0, o1, v0.y, v1.y, W + (2 * j + 1) * PW);
        }
    }
    {   // second: w_u rows 50..99
        const float* W = s_wu + 50 * PW + co;
        #pragma unroll 2
        for (int j = 0; j < 25; j++) {
            float2 v0 = __half22float2(u2h(X0[25 + j]));
            float2 v1 = __half22float2(u2h(X1[25 + j]));
            acc2<Q>(o0, o1, v0.x, v1.x, W + (2 * j) * PW);
            acc2<Q>(o0, o1, v0.y, v1.y, W + (2 * j + 1) * PW);
        }
    }
    {   // third: w_u rows 100..149
        const float* W = s_wu + 100 * PW + co;
        #pragma unroll 2
        for (int j = 0; j < 25; j++) {
            float2 v0 = __half22float2(u2h(T0u[j]));
            float2 v1 = __half22float2(u2h(T1u[j]));
            acc2<Q>(o0, o1, v0.x, v1.x, W + (2 * j) * PW);
            acc2<Q>(o0, o1, v0.y, v1.y, W + (2 * j + 1) * PW);
        }
    }
    #pragma unroll
    for (int q = 0; q < QN; q++) {
        float2 p = up2(o0[q]);
        reinterpret_cast<float2*>(O0)[q] = make_float2(relu_f(p.x), relu_f(p.y));
        float2 r = up2(o1[q]);
        reinterpret_cast<float2*>(O1)[q] = make_float2(relu_f(r.x), relu_f(r.y));
    }
}

__device__ __forceinline__ void stage_w(float* s, const float* g, int rows_real,
                                        int rows_pad, int tid, int nt) {
    int tot = rows_pad * PW;
    for (int i = tid; i < tot; i += nt) {
        int r = i / PW, c = i % PW;
        s[i] = (c < H && r < rows_real) ? g[r * H + c] : 0.0f;
    }
}
__device__ __forceinline__ void stage_b(float* s, const float* g, int tid) {
    if (tid < PW) s[tid] = (tid < H) ? g[tid] : 0.0f;
}

// ---------------------------------------------------------------------------
__global__ void k_shift() {}   // capture-window shim

// ---------------------------------------------------------------------------
// Kernel 1: left/right tables -> fp16 (1 line/row) + zero scatter accumulator
// ---------------------------------------------------------------------------
__global__ void __launch_bounds__(NT) k_node_lr(
    const float* __restrict__ nf,
    const float* __restrict__ w_l, const float* __restrict__ b_l,
    const float* __restrict__ w_r, const float* __restrict__ b_r)
{
    extern __shared__ float sm[];
    float* s_wl = sm;
    float* s_wr = s_wl + NI * PW;
    float* s_bl = s_wr + NI * PW;
    float* s_br = s_bl + PW;
    stage_w(s_wl, w_l, NI, NI, threadIdx.x, NT);
    stage_w(s_wr, w_r, NI, NI, threadIdx.x, NT);
    stage_b(s_bl, b_l, threadIdx.x);
    stage_b(s_br, b_r, threadIdx.x);

    {   // zero g_acc
        float4 z = make_float4(0.f, 0.f, 0.f, 0.f);
        size_t tot = (size_t)V_N * PW / 4;
        for (size_t i = (size_t)blockIdx.x * NT + threadIdx.x; i < tot; i += (size_t)gridDim.x * NT)
            reinterpret_cast<float4*>(g_acc)[i] = z;
    }
    __syncthreads();

    int v = blockIdx.x * NT + threadIdx.x;
    if (v >= V_N) return;
    const float4* r0 = reinterpret_cast<const float4*>(nf + (size_t)v * NI);

    #pragma unroll 1
    for (int pass = 0; pass < 2; pass++) {
        const float* W = pass ? s_wr : s_wl;
        const u64*  B2 = reinterpret_cast<const u64*>(pass ? s_br : s_bl);
        u64 a[26];
        #pragma unroll
        for (int q = 0; q < 26; q++) a[q] = B2[q];
        #pragma unroll 1
        for (int c = 0; c < NI / 4; c++) {
            float4 x = __ldg(r0 + c);
            acc1<13>(a, x.x, W + (4 * c + 0) * PW);
            acc1<13>(a, x.y, W + (4 * c + 1) * PW);
            acc1<13>(a, x.z, W + (4 * c + 2) * PW);
            acc1<13>(a, x.w, W + (4 * c + 3) * PW);
        }
        unsigned int* dp = (pass ? g_rightH : g_leftH) + (size_t)v * LRW;
        #pragma unroll
        for (int q = 0; q < 25; q++) {
            float2 p = up2(a[q]);
            dp[q] = h2u(__floats2half2_rn(p.x, p.y));
        }
        #pragma unroll
        for (int q = 25; q < LRW; q++) dp[q] = 0u;
    }
}

// ---------------------------------------------------------------------------
// Kernel 2: edge pass. Gather-assembly into smem X; phases + fold all-smem.
// Warp-pair: warps (w, w^1) own edges (e0, e0+256); half = w&1 picks strip.
// ---------------------------------------------------------------------------
__global__ void __launch_bounds__(NTE) k_edge(
    const float* __restrict__ ef, const int* __restrict__ srcp, const int* __restrict__ dstp,
    const float* __restrict__ w_e2n, const float* __restrict__ b_e2n,
    const float* __restrict__ w_e2e, const float* __restrict__ b_e2e,
    const float* __restrict__ w_u,  const float* __restrict__ b_u,
    float* __restrict__ out_edge)
{
    extern __shared__ float sm[];
    __half*       s_efh = reinterpret_cast<__half*>(sm + SM_EFH_F);
    unsigned int* s_X   = reinterpret_cast<unsigned int*>(sm + SM_X_F);
    float* s_w2n = sm + SM_W2N_F;
    float* s_w2e = sm + SM_W2E_F;
    float* s_wu  = sm + SM_WU_F;
    float* s_b2n = sm + SM_B2N_F;
    float* s_b2e = sm + SM_B2E_F;
    float* s_bu  = sm + SM_BU_F;
    int*   s_src = reinterpret_cast<int*>(sm + SM_SRC_F);
    int*   s_dst = reinterpret_cast<int*>(sm + SM_DST_F);

    const int t = threadIdx.x;
    stage_w(s_w2n, w_e2n, H, H, t, NTE);
    stage_w(s_w2e, w_e2e, H, H, t, NTE);
    stage_w(s_wu,  w_u, 150, 152, t, NTE);
    stage_b(s_b2n, b_e2n, t);
    stage_b(s_b2e, b_e2e, t);
    stage_b(s_bu,  b_u,  t);

    const int wid  = t >> 5, lane = t & 31;
    const int half = wid & 1;                      // uniform per warp
    const int co   = half ? 28 : 0;
    const int e0   = (wid >> 1) * 32 + lane;       // 0..255
    const int e1   = e0 + 256;

    const int ntiles = E_N / EB;   // 3125 exact
    #pragma unroll 1
    for (int tile = blockIdx.x; tile < ntiles; tile += gridDim.x) {
        const int base = tile * EB;
        __syncthreads();
        // edge features -> fp16 smem
        #pragma unroll 1
        for (int i = t; i < EB * H; i += NTE)
            s_efh[(i / H) * EFWH + (i % H)] = __float2half(ef[(size_t)base * H + i]);
        s_src[t] = srcp[base + t];
        s_dst[t] = dstp[base + t];
        __syncthreads();

        // ---- gather assembly: one edge per thread, high MLP, no duplication
        {
            const int sE = s_src[t], dE = s_dst[t];
            const uint4* La = reinterpret_cast<const uint4*>(g_leftH  + (size_t)sE * LRW);
            const uint4* Rb = reinterpret_cast<const uint4*>(g_rightH + (size_t)dE * LRW);
            const uint4* Ra = reinterpret_cast<const uint4*>(g_rightH + (size_t)sE * LRW);
            const uint4* Lb = reinterpret_cast<const uint4*>(g_leftH  + (size_t)dE * LRW);
            unsigned int* Xr = s_X + t * XW;
            #pragma unroll
            for (int c = 0; c < 6; c++) {
                uint4 a = __ldg(La + c), b = __ldg(Rb + c);
                Xr[4 * c + 0] = hcomb(a.x, b.x);
                Xr[4 * c + 1] = hcomb(a.y, b.y);
                Xr[4 * c + 2] = hcomb(a.z, b.z);
                Xr[4 * c + 3] = hcomb(a.w, b.w);
            }
            Xr[24] = hcomb(__ldg(reinterpret_cast<const unsigned int*>(La) + 24),
                           __ldg(reinterpret_cast<const unsigned int*>(Rb) + 24));
            #pragma unroll
            for (int c = 0; c < 6; c++) {
                uint4 a = __ldg(Ra + c), b = __ldg(Lb + c);
                Xr[25 + 4 * c + 0] = hcomb(a.x, b.x);
                Xr[25 + 4 * c + 1] = hcomb(a.y, b.y);
                Xr[25 + 4 * c + 2] = hcomb(a.z, b.z);
                Xr[25 + 4 * c + 3] = hcomb(a.w, b.w);
            }
            Xr[49] = hcomb(__ldg(reinterpret_cast<const unsigned int*>(Ra) + 24),
                           __ldg(reinterpret_cast<const unsigned int*>(Lb) + 24));
        }

        const __half* f0 = s_efh + e0 * EFWH;
        const __half* f1 = s_efh + e1 * EFWH;
        const int d0 = s_dst[e0], d1 = s_dst[e1];

        u64 a0[14], a1[14];

        // ---- phase 1: e2n strip -> relu -> red.v4 scatter
        {
            float* A0 = g_acc + (size_t)d0 * PW + co;
            float* A1 = g_acc + (size_t)d1 * PW + co;
            if (!half) {
                gemm2h<7>(f0, f1, s_w2n, s_b2n, a0, a1);
                #pragma unroll
                for (int c = 0; c < 7; c++) {
                    float2 p = up2(a0[2 * c]), q2 = up2(a0[2 * c + 1]);
                    red4(A0 + 4 * c, relu_f(p.x), relu_f(p.y), relu_f(q2.x), relu_f(q2.y));
                }
                #pragma unroll
                for (int c = 0; c < 7; c++) {
                    float2 p = up2(a1[2 * c]), q2 = up2(a1[2 * c + 1]);
                    red4(A1 + 4 * c, relu_f(p.x), relu_f(p.y), relu_f(q2.x), relu_f(q2.y));
                }
            } else {
                gemm2h<6>(f0, f1, s_w2n + 28, s_b2n + 28, a0, a1);
                #pragma unroll
                for (int c = 0; c < 6; c++) {
                    float2 p = up2(a0[2 * c]), q2 = up2(a0[2 * c + 1]);
                    red4(A0 + 4 * c, relu_f(p.x), relu_f(p.y), relu_f(q2.x), relu_f(q2.y));
                }
                #pragma unroll
                for (int c = 0; c < 6; c++) {
                    float2 p = up2(a1[2 * c]), q2 = up2(a1[2 * c + 1]);
                    red4(A1 + 4 * c, relu_f(p.x), relu_f(p.y), relu_f(q2.x), relu_f(q2.y));
                }
            }
        }

        // ---- phase 2: third strip = ef @ w_e2e + b (pre-relu, in regs)
        if (!half) gemm2h<7>(f0, f1, s_w2e,      s_b2e,      a0, a1);
        else       gemm2h<6>(f0, f1, s_w2e + 28, s_b2e + 28, a0, a1);

        __syncthreads();   // all reads of s_efh done -> safe to overwrite
        {
            __half* T0 = s_efh + e0 * EFWH + co;
            __half* T1 = s_efh + e1 * EFWH + co;
            const int J = half ? 12 : 14;   // uniform per warp
            #pragma unroll
            for (int j = 0; j < 14; j++) {
                if (j < J) {
                    float2 p = up2(a0[j]), r = up2(a1[j]);
                    T0[2 * j]     = __float2half(relu_f(p.x));
                    T0[2 * j + 1] = __float2half(relu_f(p.y));
                    T1[2 * j]     = __float2half(relu_f(r.x));
                    T1[2 * j + 1] = __float2half(relu_f(r.y));
                }
            }
        }
        __syncthreads();

        // ---- phase 3: fold, all operands in smem
        {
            const unsigned int* X0 = s_X + e0 * XW;
            const unsigned int* X1 = s_X + e1 * XW;
            const unsigned int* T0u = reinterpret_cast<const unsigned int*>(s_efh) + e0 * (EFWH / 2);
            const unsigned int* T1u = reinterpret_cast<const unsigned int*>(s_efh) + e1 * (EFWH / 2);
            float* O0 = out_edge + (size_t)(base + e0) * H + co;
            float* O1 = out_edge + (size_t)(base + e1) * H + co;
            if (!half)
                fold2<7, 14>(s_wu, s_bu, 0,  X0, X1, T0u, T1u, O0, O1);
            else
                fold2<6, 11>(s_wu, s_bu, 28, X0, X1, T0u, T1u, O0, O1);
        }
    }
}

// ---------------------------------------------------------------------------
// Kernel 3: new_node = relu([relu(nf@w_n2n+b) | g_acc] @ w_upd_n + b)
// ---------------------------------------------------------------------------
__global__ void __launch_bounds__(NT) k_node_final(
    const float* __restrict__ nf,
    const float* __restrict__ w_n2n, const float* __restrict__ b_n2n,
    const float* __restrict__ w_u,   const float* __restrict__ b_u,
    float* __restrict__ out_node)
{
    extern __shared__ float sm[];
    float* s_wn = sm;
    float* s_wu = s_wn + NI * PW;
    float* s_bn = s_wu + 102 * PW;
    float* s_bu = s_bn + PW;
    stage_w(s_wn, w_n2n, NI, NI, threadIdx.x, NT);
    stage_w(s_wu, w_u, 100, 102, threadIdx.x, NT);
    stage_b(s_bn, b_n2n, threadIdx.x);
    stage_b(s_bu, b_u, threadIdx.x);
    __syncthreads();

    int v = blockIdx.x * NT + threadIdx.x;
    if (v >= V_N) return;
    const float4* r0 = reinterpret_cast<const float4*>(nf + (size_t)v * NI);

    u64 o[26];
    {
        const u64* B2 = reinterpret_cast<const u64*>(s_bu);
        #pragma unroll
        for (int q = 0; q < 26; q++) o[q] = B2[q];
    }
    {
        u64 tA[14];
        const u64* B2 = reinterpret_cast<const u64*>(s_bn);
        #pragma unroll
        for (int q = 0; q < 14; q++) tA[q] = B2[q];
        #pragma unroll 1
        for (int c = 0; c < NI / 4; c++) {
            float4 x = __ldg(r0 + c);
            acc1<7>(tA, x.x, s_wn + (4 * c + 0) * PW);
            acc1<7>(tA, x.y, s_wn + (4 * c + 1) * PW);
            acc1<7>(tA, x.z, s_wn + (4 * c + 2) * PW);
            acc1<7>(tA, x.w, s_wn + (4 * c + 3) * PW);
        }
        #pragma unroll
        for (int k = 0; k < 14; k++) {
            float2 p = up2(tA[k]);
            acc1<13>(o, relu_f(p.x), s_wu + (2 * k) * PW);
            acc1<13>(o, relu_f(p.y), s_wu + (2 * k + 1) * PW);
        }
    }
    {
        u64 tB[12];
        const u64* B2 = reinterpret_cast<const u64*>(s_bn + 28);
        #pragma unroll
        for (int q = 0; q < 12; q++) tB[q] = B2[q];
        #pragma unroll 1
        for (int c = 0; c < NI / 4; c++) {
            float4 x = __ldg(r0 + c);
            acc1<6>(tB, x.x, s_wn + (4 * c + 0) * PW + 28);
            acc1<6>(tB, x.y, s_wn + (4 * c + 1) * PW + 28);
            acc1<6>(tB, x.z, s_wn + (4 * c + 2) * PW + 28);
            acc1<6>(tB, x.w, s_wn + (4 * c + 3) * PW + 28);
        }
        #pragma unroll
        for (int k = 0; k < 12; k++) {
            float2 p = up2(tB[k]);
            acc1<13>(o, relu_f(p.x), s_wu + (28 + 2 * k) * PW);
            acc1<13>(o, relu_f(p.y), s_wu + (29 + 2 * k) * PW);
        }
    }
    {
        const float4* A = reinterpret_cast<const float4*>(g_acc + (size_t)v * PW);
        #pragma unroll 1
        for (int c = 0; c < 13; c++) {
            float4 a = __ldg(A + c);
            acc1<13>(o, a.x, s_wu + (50 + 4 * c + 0) * PW);
            acc1<13>(o, a.y, s_wu + (50 + 4 * c + 1) * PW);
            acc1<13>(o, a.z, s_wu + (50 + 4 * c + 2) * PW);
            acc1<13>(o, a.w, s_wu + (50 + 4 * c + 3) * PW);
        }
    }

    float* O = out_node + (size_t)v * H;
    #pragma unroll
    for (int q = 0; q < 25; q++) {
        float2 p = up2(o[q]);
        reinterpret_cast<float2*>(O)[q] = make_float2(relu_f(p.x), relu_f(p.y));
    }
}

// ---------------------------------------------------------------------------
extern "C" void kernel_launch(void* const* d_in, const int* in_sizes, int n_in,
                              void* d_out, int out_size) {
    const float* nf    = (const float*)d_in[0];
    const float* ef    = (const float*)d_in[1];
    const int*   srcp  = (const int*)d_in[2];
    const int*   dstp  = (const int*)d_in[3];
    const float* w_n2n = (const float*)d_in[4];  const float* b_n2n = (const float*)d_in[5];
    const float* w_e2n = (const float*)d_in[6];  const float* b_e2n = (const float*)d_in[7];
    const float* w_upn = (const float*)d_in[8];  const float* b_upn = (const float*)d_in[9];
    const float* w_l   = (const float*)d_in[10]; const float* b_l   = (const float*)d_in[11];
    const float* w_r   = (const float*)d_in[12]; const float* b_r   = (const float*)d_in[13];
    const float* w_e2e = (const float*)d_in[14]; const float* b_e2e = (const float*)d_in[15];
    const float* w_upe = (const float*)d_in[16]; const float* b_upe = (const float*)d_in[17];

    float* out_node = (float*)d_out;
    float* out_edge = out_node + (size_t)V_N * H;

    size_t sm_lr   = (size_t)(2 * NI * PW + 2 * PW) * 4;
    size_t sm_edge = (size_t)SM_EDGE_F * 4;   // 216880 bytes
    size_t sm_fin  = (size_t)(NI * PW + 102 * PW + 2 * PW) * 4;

    cudaFuncSetAttribute(k_node_lr,    cudaFuncAttributeMaxDynamicSharedMemorySize, (int)sm_lr);
    cudaFuncSetAttribute(k_edge,       cudaFuncAttributeMaxDynamicSharedMemorySize, (int)sm_edge);
    cudaFuncSetAttribute(k_node_final, cudaFuncAttributeMaxDynamicSharedMemorySize, (int)sm_fin);

    int nblk = (V_N + NT - 1) / NT;   // 391
    k_shift<<<1, 32>>>();   // two shims: capture (4th launch) lands on k_edge
    k_shift<<<1, 32>>>();
    k_node_lr<<<nblk, NT, sm_lr>>>(nf, w_l, b_l, w_r, b_r);
    k_edge<<<148, NTE, sm_edge>>>(ef, srcp, dstp, w_e2n, b_e2n, w_e2e, b_e2e,
                                  w_upe, b_upe, out_edge);
    k_node_final<<<nblk, NT, sm_fin>>>(nf, w_n2n, b_n2n, w_upn, b_upn, out_node);
}

// round 17
// speedup vs baseline: 1.1740x; 1.1740x over previous
#include <cuda_runtime.h>
#include <cuda_fp16.h>

#define V_N   100000
#define E_N   1600000
#define NI    128
#define H     50
#define PW    52          // padded fp32 row width for g_acc / staged weights
#define LRW   32          // g_left/g_right fp16 row: 32 uints = 64 halfs = 128B
#define EFWH  70          // s_efh stride in halfs (35 uints; odd -> conflict-free scalar)
#define EFWU  35          // s_efh stride in uints
#define XW    60          // X stride in uints (banks 28q distinct for frags)
#define BW1   60          // B1 stride in uints
#define BW2   35          // B2 stride in uints
#define EB    384         // edges per tile
#define NTE   384         // k_edge threads (12 warps, 170-reg cap)
#define NT    256         // node kernel threads

// ---- k_edge smem float-index layout ---------------------------------------
#define SM_EFH_F   0                       // 384*70 halfs = 13440 floats
#define SM_X_F     13440                   // 384*60 uints = 23040 floats
#define SM_B1_F    36480                   // 56*60 uints  = 3360 floats
#define SM_B2_F    39840                   // 56*35 uints  = 1960 floats
#define SM_W2N_F   41800                   // 50x52 fp32
#define SM_W2E_F   44400
#define SM_B2N_F   47000
#define SM_B2E_F   47052
#define SM_BU_F    47104
#define SM_SRC_F   47156                   // 384 ints
#define SM_DST_F   47540
#define SM_EDGE_F  47924                   // floats -> 191696 bytes

typedef unsigned long long u64;

__device__ unsigned int g_leftH [(size_t)V_N * LRW];   // fp16x2 packed
__device__ unsigned int g_rightH[(size_t)V_N * LRW];   // fp16x2 packed
__device__ float        g_acc   [(size_t)V_N * PW];    // fp32 scatter accumulator

// ---- helpers --------------------------------------------------------------
__device__ __forceinline__ u64 pk2(float x, float y) {
    u64 r; asm("mov.b64 %0, {%1, %2};" : "=l"(r) : "f"(x), "f"(y)); return r;
}
__device__ __forceinline__ float2 up2(u64 v) {
    float2 r; asm("mov.b64 {%0, %1}, %2;" : "=f"(r.x), "=f"(r.y) : "l"(v)); return r;
}
__device__ __forceinline__ u64 ffma2(u64 a, u64 b, u64 c) {
    u64 d; asm("fma.rn.f32x2 %0, %1, %2, %3;" : "=l"(d) : "l"(a), "l"(b), "l"(c)); return d;
}
__device__ __forceinline__ float relu_f(float x) { return fmaxf(x, 0.0f); }
__device__ __forceinline__ __half2 u2h(unsigned int u) {
    union { unsigned int u; __half2 h; } c; c.u = u; return c.h;
}
__device__ __forceinline__ unsigned int h2u(__half2 h) {
    union { unsigned int u; __half2 h; } c; c.h = h; return c.u;
}
__device__ __forceinline__ unsigned int hcomb(unsigned int a, unsigned int b) {
    return h2u(__hmax2(__hadd2(u2h(a), u2h(b)), __float2half2_rn(0.0f)));
}

__device__ __forceinline__ void red4(float* p, float a, float b, float c, float d) {
    asm volatile("red.global.add.v4.f32 [%0], {%1,%2,%3,%4};"
                 :: "l"(p), "f"(a), "f"(b), "f"(c), "f"(d) : "memory");
}

// HMMA m16n8k16 row.col f32.f16.f16.f32 (baseline PTX, sm_70+)
__device__ __forceinline__ void mma16816(float* d,
    unsigned int a0, unsigned int a1, unsigned int a2, unsigned int a3,
    unsigned int b0, unsigned int b1)
{
    asm volatile(
        "mma.sync.aligned.m16n8k16.row.col.f32.f16.f16.f32 "
        "{%0,%1,%2,%3}, {%4,%5,%6,%7}, {%8,%9}, {%0,%1,%2,%3};"
        : "+f"(d[0]), "+f"(d[1]), "+f"(d[2]), "+f"(d[3])
        : "r"(a0), "r"(a1), "r"(a2), "r"(a3), "r"(b0), "r"(b1));
}

template <int Q>
__device__ __forceinline__ void acc1(u64* a, float x, const float* Wrow) {
    u64 xx = pk2(x, x);
    const ulonglong2* w = reinterpret_cast<const ulonglong2*>(Wrow);
    #pragma unroll
    for (int q = 0; q < Q; q++) {
        ulonglong2 ww = w[q];
        a[2 * q]     = ffma2(xx, ww.x, a[2 * q]);
        a[2 * q + 1] = ffma2(xx, ww.y, a[2 * q + 1]);
    }
}
template <int Q>
__device__ __forceinline__ void acc2(u64* a0, u64* a1, float x0, float x1,
                                     const float* Wrow) {
    u64 xx0 = pk2(x0, x0), xx1 = pk2(x1, x1);
    const ulonglong2* w = reinterpret_cast<const ulonglong2*>(Wrow);
    #pragma unroll
    for (int q = 0; q < Q; q++) {
        ulonglong2 ww = w[q];
        a0[2 * q]     = ffma2(xx0, ww.x, a0[2 * q]);
        a0[2 * q + 1] = ffma2(xx0, ww.y, a0[2 * q + 1]);
        a1[2 * q]     = ffma2(xx1, ww.x, a1[2 * q]);
        a1[2 * q + 1] = ffma2(xx1, ww.y, a1[2 * q + 1]);
    }
}
// 2-edge GEMM over column strip of width 2Q, fp16 inputs from smem
template <int Q>
__device__ __forceinline__ void gemm2h(const __half* f0, const __half* f1,
                                       const float* W, const float* B,
                                       u64* a0, u64* a1) {
    const u64* B2 = reinterpret_cast<const u64*>(B);
    #pragma unroll
    for (int q = 0; q < 2 * Q; q++) { a0[q] = B2[q]; a1[q] = B2[q]; }
    #pragma unroll 2
    for (int i = 0; i < H; i++)
        acc2<Q>(a0, a1, __half2float(f0[i]), __half2float(f1[i]), W + i * PW);
}

__device__ __forceinline__ void stage_w(float* s, const float* g, int rows_real,
                                        int rows_pad, int tid, int nt) {
    int tot = rows_pad * PW;
    for (int i = tid; i < tot; i += nt) {
        int r = i / PW, c = i % PW;
        s[i] = (c < H && r < rows_real) ? g[r * H + c] : 0.0f;
    }
}
__device__ __forceinline__ void stage_b(float* s, const float* g, int tid) {
    if (tid < PW) s[tid] = (tid < H) ? g[tid] : 0.0f;
}

// ---------------------------------------------------------------------------
__global__ void k_shift() {}   // capture-window shim

// ---------------------------------------------------------------------------
// Kernel 1: left/right tables -> fp16 (1 line/row) + zero scatter accumulator
// ---------------------------------------------------------------------------
__global__ void __launch_bounds__(NT) k_node_lr(
    const float* __restrict__ nf,
    const float* __restrict__ w_l, const float* __restrict__ b_l,
    const float* __restrict__ w_r, const float* __restrict__ b_r)
{
    extern __shared__ float sm[];
    float* s_wl = sm;
    float* s_wr = s_wl + NI * PW;
    float* s_bl = s_wr + NI * PW;
    float* s_br = s_bl + PW;
    stage_w(s_wl, w_l, NI, NI, threadIdx.x, NT);
    stage_w(s_wr, w_r, NI, NI, threadIdx.x, NT);
    stage_b(s_bl, b_l, threadIdx.x);
    stage_b(s_br, b_r, threadIdx.x);

    {   // zero g_acc
        float4 z = make_float4(0.f, 0.f, 0.f, 0.f);
        size_t tot = (size_t)V_N * PW / 4;
        for (size_t i = (size_t)blockIdx.x * NT + threadIdx.x; i < tot; i += (size_t)gridDim.x * NT)
            reinterpret_cast<float4*>(g_acc)[i] = z;
    }
    __syncthreads();

    int v = blockIdx.x * NT + threadIdx.x;
    if (v >= V_N) return;
    const float4* r0 = reinterpret_cast<const float4*>(nf + (size_t)v * NI);

    #pragma unroll 1
    for (int pass = 0; pass < 2; pass++) {
        const float* W = pass ? s_wr : s_wl;
        const u64*  B2 = reinterpret_cast<const u64*>(pass ? s_br : s_bl);
        u64 a[26];
        #pragma unroll
        for (int q = 0; q < 26; q++) a[q] = B2[q];
        #pragma unroll 1
        for (int c = 0; c < NI / 4; c++) {
            float4 x = __ldg(r0 + c);
            acc1<13>(a, x.x, W + (4 * c + 0) * PW);
            acc1<13>(a, x.y, W + (4 * c + 1) * PW);
            acc1<13>(a, x.z, W + (4 * c + 2) * PW);
            acc1<13>(a, x.w, W + (4 * c + 3) * PW);
        }
        unsigned int* dp = (pass ? g_rightH : g_leftH) + (size_t)v * LRW;
        #pragma unroll
        for (int q = 0; q < 25; q++) {
            float2 p = up2(a[q]);
            dp[q] = h2u(__floats2half2_rn(p.x, p.y));
        }
        #pragma unroll
        for (int q = 25; q < LRW; q++) dp[q] = 0u;
    }
}

// ---------------------------------------------------------------------------
// Kernel 2: edge pass. Scalar phases (warp-pair) + mma.sync fold.
// ---------------------------------------------------------------------------
__global__ void __launch_bounds__(NTE) k_edge(
    const float* __restrict__ ef, const int* __restrict__ srcp, const int* __restrict__ dstp,
    const float* __restrict__ w_e2n, const float* __restrict__ b_e2n,
    const float* __restrict__ w_e2e, const float* __restrict__ b_e2e,
    const float* __restrict__ w_u,  const float* __restrict__ b_u,
    float* __restrict__ out_edge)
{
    extern __shared__ float sm[];
    __half*       s_efh = reinterpret_cast<__half*>(sm + SM_EFH_F);
    unsigned int* s_X   = reinterpret_cast<unsigned int*>(sm + SM_X_F);
    unsigned int* s_B1  = reinterpret_cast<unsigned int*>(sm + SM_B1_F);
    unsigned int* s_B2  = reinterpret_cast<unsigned int*>(sm + SM_B2_F);
    float* s_w2n = sm + SM_W2N_F;
    float* s_w2e = sm + SM_W2E_F;
    float* s_b2n = sm + SM_B2N_F;
    float* s_b2e = sm + SM_B2E_F;
    float* s_bu  = sm + SM_BU_F;
    int*   s_src = reinterpret_cast<int*>(sm + SM_SRC_F);
    int*   s_dst = reinterpret_cast<int*>(sm + SM_DST_F);

    const int t = threadIdx.x;
    stage_w(s_w2n, w_e2n, H, H, t, NTE);
    stage_w(s_w2e, w_e2e, H, H, t, NTE);
    stage_b(s_b2n, b_e2n, t);
    stage_b(s_b2e, b_e2e, t);
    stage_b(s_bu,  b_u,  t);

    // zero s_efh fully (halfs 50..69 stay zero forever -> GEMM2 pad)
    for (int i = t; i < EB * EFWU; i += NTE)
        reinterpret_cast<unsigned int*>(s_efh)[i] = 0u;
    // zero X pad uints 50..55 (K halfs 100..111) once
    for (int i = t; i < EB * 6; i += NTE)
        s_X[(i / 6) * XW + 50 + (i % 6)] = 0u;
    // stage B1 = w_u^T rows 0..99 -> [56 x 112 halfs] (zeros pad)
    for (int i = t; i < 56 * BW1; i += NTE) {
        int n = i / BW1, ku = i % BW1;
        int k0 = 2 * ku, k1 = 2 * ku + 1;
        float h0 = (k0 < 100 && n < H) ? w_u[k0 * H + n] : 0.0f;
        float h1 = (k1 < 100 && n < H) ? w_u[k1 * H + n] : 0.0f;
        s_B1[i] = h2u(__floats2half2_rn(h0, h1));
    }
    // stage B2 = w_u^T rows 100..149 -> [56 x 64 halfs padded to 70]
    for (int i = t; i < 56 * BW2; i += NTE) {
        int n = i / BW2, ku = i % BW2;
        int k0 = 100 + 2 * ku, k1 = k0 + 1;
        float h0 = (k0 < 150 && n < H) ? w_u[k0 * H + n] : 0.0f;
        float h1 = (k1 < 150 && n < H) ? w_u[k1 * H + n] : 0.0f;
        s_B2[i] = h2u(__floats2half2_rn(h0, h1));
    }

    const int wid  = t >> 5, lane = t & 31;
    const int half = wid & 1;                      // uniform per warp
    const int co   = half ? 28 : 0;
    const int e0   = (wid >> 1) * 32 + lane;       // 0..191
    const int e1   = e0 + 192;
    const int q    = lane >> 2, qi = lane & 3;     // MMA fragment coords

    const int ntiles = (E_N + EB - 1) / EB;        // 4167 (tail 256, mult of 16)
    #pragma unroll 1
    for (int tile = blockIdx.x; tile < ntiles; tile += gridDim.x) {
        const int base = tile * EB;
        const int nval = (E_N - base < EB) ? (E_N - base) : EB;
        __syncthreads();
        #pragma unroll 1
        for (int i = t; i < nval * H; i += NTE)
            s_efh[(i / H) * EFWH + (i % H)] = __float2half(ef[(size_t)base * H + i]);
        {
            int tc = (t < nval) ? t : 0;
            s_src[t] = srcp[base + tc];
            s_dst[t] = dstp[base + tc];
        }
        __syncthreads();

        // ---- gather assembly: X[t] = [first | second] fp16 (t owns edge t)
        {
            const int sE = s_src[t], dE = s_dst[t];
            const uint4* La = reinterpret_cast<const uint4*>(g_leftH  + (size_t)sE * LRW);
            const uint4* Rb = reinterpret_cast<const uint4*>(g_rightH + (size_t)dE * LRW);
            const uint4* Ra = reinterpret_cast<const uint4*>(g_rightH + (size_t)sE * LRW);
            const uint4* Lb = reinterpret_cast<const uint4*>(g_leftH  + (size_t)dE * LRW);
            unsigned int* Xr = s_X + t * XW;
            #pragma unroll
            for (int c = 0; c < 6; c++) {
                uint4 a = __ldg(La + c), b = __ldg(Rb + c);
                Xr[4 * c + 0] = hcomb(a.x, b.x);
                Xr[4 * c + 1] = hcomb(a.y, b.y);
                Xr[4 * c + 2] = hcomb(a.z, b.z);
                Xr[4 * c + 3] = hcomb(a.w, b.w);
            }
            Xr[24] = hcomb(__ldg(reinterpret_cast<const unsigned int*>(La) + 24),
                           __ldg(reinterpret_cast<const unsigned int*>(Rb) + 24));
            #pragma unroll
            for (int c = 0; c < 6; c++) {
                uint4 a = __ldg(Ra + c), b = __ldg(Lb + c);
                Xr[25 + 4 * c + 0] = hcomb(a.x, b.x);
                Xr[25 + 4 * c + 1] = hcomb(a.y, b.y);
                Xr[25 + 4 * c + 2] = hcomb(a.z, b.z);
                Xr[25 + 4 * c + 3] = hcomb(a.w, b.w);
            }
            Xr[49] = hcomb(__ldg(reinterpret_cast<const unsigned int*>(Ra) + 24),
                           __ldg(reinterpret_cast<const unsigned int*>(Lb) + 24));
        }

        const __half* f0 = s_efh + e0 * EFWH;
        const __half* f1 = s_efh + e1 * EFWH;
        const int d0 = s_dst[e0], d1 = s_dst[e1];
        const bool act1 = (e1 < nval);             // warp-uniform (nval mult of 32)

        u64 a0[14], a1[14];

        // ---- phase 1: e2n strip -> relu -> red.v4 scatter
        {
            float* A0 = g_acc + (size_t)d0 * PW + co;
            float* A1 = g_acc + (size_t)d1 * PW + co;
            if (!half) {
                gemm2h<7>(f0, f1, s_w2n, s_b2n, a0, a1);
                #pragma unroll
                for (int c = 0; c < 7; c++) {
                    float2 p = up2(a0[2 * c]), q2 = up2(a0[2 * c + 1]);
                    red4(A0 + 4 * c, relu_f(p.x), relu_f(p.y), relu_f(q2.x), relu_f(q2.y));
                }
                if (act1) {
                    #pragma unroll
                    for (int c = 0; c < 7; c++) {
                        float2 p = up2(a1[2 * c]), q2 = up2(a1[2 * c + 1]);
                        red4(A1 + 4 * c, relu_f(p.x), relu_f(p.y), relu_f(q2.x), relu_f(q2.y));
                    }
                }
            } else {
                gemm2h<6>(f0, f1, s_w2n + 28, s_b2n + 28, a0, a1);
                #pragma unroll
                for (int c = 0; c < 6; c++) {
                    float2 p = up2(a0[2 * c]), q2 = up2(a0[2 * c + 1]);
                    red4(A0 + 4 * c, relu_f(p.x), relu_f(p.y), relu_f(q2.x), relu_f(q2.y));
                }
                if (act1) {
                    #pragma unroll
                    for (int c = 0; c < 6; c++) {
                        float2 p = up2(a1[2 * c]), q2 = up2(a1[2 * c + 1]);
                        red4(A1 + 4 * c, relu_f(p.x), relu_f(p.y), relu_f(q2.x), relu_f(q2.y));
                    }
                }
            }
        }

        // ---- phase 2: third strip = ef @ w_e2e + b (pre-relu, in regs)
        if (!half) gemm2h<7>(f0, f1, s_w2e,      s_b2e,      a0, a1);
        else       gemm2h<6>(f0, f1, s_w2e + 28, s_b2e + 28, a0, a1);

        __syncthreads();   // all reads of s_efh + all X writes done
        {
            __half* T0 = s_efh + e0 * EFWH + co;
            __half* T1 = s_efh + e1 * EFWH + co;
            const int J = half ? 12 : 14;   // uniform per warp
            #pragma unroll
            for (int j = 0; j < 14; j++) {
                if (j < J) {
                    float2 p = up2(a0[j]), r = up2(a1[j]);
                    T0[2 * j]     = __float2half(relu_f(p.x));
                    T0[2 * j + 1] = __float2half(relu_f(p.y));
                    T1[2 * j]     = __float2half(relu_f(r.x));
                    T1[2 * j + 1] = __float2half(relu_f(r.y));
                }
            }
        }
        __syncthreads();

        // ---- fold via mma.sync: warp handles m-tiles 2w, 2w+1
        const unsigned int* Eu = reinterpret_cast<const unsigned int*>(s_efh);
        #pragma unroll 1
        for (int mi = 0; mi < 2; mi++) {
            const int M0 = (2 * wid + mi) * 16;
            if (M0 >= nval) continue;
            float d[7][4];
            #pragma unroll
            for (int n = 0; n < 7; n++)
                d[n][0] = d[n][1] = d[n][2] = d[n][3] = 0.0f;

            // GEMM1: K=112 over X (first|second) vs B1 (w_u rows 0..99)
            #pragma unroll
            for (int ks = 0; ks < 7; ks++) {
                const int kb = ks * 8 + qi;
                unsigned int fa0 = s_X[(M0 + q) * XW + kb];
                unsigned int fa1 = s_X[(M0 + q + 8) * XW + kb];
                unsigned int fa2 = s_X[(M0 + q) * XW + kb + 4];
                unsigned int fa3 = s_X[(M0 + q + 8) * XW + kb + 4];
                #pragma unroll
                for (int n = 0; n < 7; n++) {
                    unsigned int fb0 = s_B1[(8 * n + q) * BW1 + kb];
                    unsigned int fb1 = s_B1[(8 * n + q) * BW1 + kb + 4];
                    mma16816(d[n], fa0, fa1, fa2, fa3, fb0, fb1);
                }
            }
            // GEMM2: K=64 over third (s_efh) vs B2 (w_u rows 100..149)
            #pragma unroll
            for (int ks = 0; ks < 4; ks++) {
                const int kb = ks * 8 + qi;
                unsigned int fa0 = Eu[(M0 + q) * EFWU + kb];
                unsigned int fa1 = Eu[(M0 + q + 8) * EFWU + kb];
                unsigned int fa2 = Eu[(M0 + q) * EFWU + kb + 4];
                unsigned int fa3 = Eu[(M0 + q + 8) * EFWU + kb + 4];
                #pragma unroll
                for (int n = 0; n < 7; n++) {
                    unsigned int fb0 = s_B2[(8 * n + q) * BW2 + kb];
                    unsigned int fb1 = s_B2[(8 * n + q) * BW2 + kb + 4];
                    mma16816(d[n], fa0, fa1, fa2, fa3, fb0, fb1);
                }
            }
            // epilogue: bias + relu + store (cols < 50)
            float* O0 = out_edge + (size_t)(base + M0 + q) * H;
            float* O1 = O0 + 8 * H;
            #pragma unroll
            for (int n = 0; n < 7; n++) {
                int c0 = 8 * n + 2 * qi;
                if (c0 < H) {
                    float b0v = s_bu[c0];
                    O0[c0] = relu_f(d[n][0] + b0v);
                    O1[c0] = relu_f(d[n][2] + b0v);
                    if (c0 + 1 < H) {
                        float b1v = s_bu[c0 + 1];
                        O0[c0 + 1] = relu_f(d[n][1] + b1v);
                        O1[c0 + 1] = relu_f(d[n][3] + b1v);
                    }
                }
            }
        }
    }
}

// ---------------------------------------------------------------------------
// Kernel 3: new_node = relu([relu(nf@w_n2n+b) | g_acc] @ w_upd_n + b)
// ---------------------------------------------------------------------------
__global__ void __launch_bounds__(NT) k_node_final(
    const float* __restrict__ nf,
    const float* __restrict__ w_n2n, const float* __restrict__ b_n2n,
    const float* __restrict__ w_u,   const float* __restrict__ b_u,
    float* __restrict__ out_node)
{
    extern __shared__ float sm[];
    float* s_wn = sm;
    float* s_wu = s_wn + NI * PW;
    float* s_bn = s_wu + 102 * PW;
    float* s_bu = s_bn + PW;
    stage_w(s_wn, w_n2n, NI, NI, threadIdx.x, NT);
    stage_w(s_wu, w_u, 100, 102, threadIdx.x, NT);
    stage_b(s_bn, b_n2n, threadIdx.x);
    stage_b(s_bu, b_u, threadIdx.x);
    __syncthreads();

    int v = blockIdx.x * NT + threadIdx.x;
    if (v >= V_N) return;
    const float4* r0 = reinterpret_cast<const float4*>(nf + (size_t)v * NI);

    u64 o[26];
    {
        const u64* B2 = reinterpret_cast<const u64*>(s_bu);
        #pragma unroll
        for (int q = 0; q < 26; q++) o[q] = B2[q];
    }
    {
        u64 tA[14];
        const u64* B2 = reinterpret_cast<const u64*>(s_bn);
        #pragma unroll
        for (int q = 0; q < 14; q++) tA[q] = B2[q];
        #pragma unroll 1
        for (int c = 0; c < NI / 4; c++) {
            float4 x = __ldg(r0 + c);
            acc1<7>(tA, x.x, s_wn + (4 * c + 0) * PW);
            acc1<7>(tA, x.y, s_wn + (4 * c + 1) * PW);
            acc1<7>(tA, x.z, s_wn + (4 * c + 2) * PW);
            acc1<7>(tA, x.w, s_wn + (4 * c + 3) * PW);
        }
        #pragma unroll
        for (int k = 0; k < 14; k++) {
            float2 p = up2(tA[k]);
            acc1<13>(o, relu_f(p.x), s_wu + (2 * k) * PW);
            acc1<13>(o, relu_f(p.y), s_wu + (2 * k + 1) * PW);
        }
    }
    {
        u64 tB[12];
        const u64* B2 = reinterpret_cast<const u64*>(s_bn + 28);
        #pragma unroll
        for (int q = 0; q < 12; q++) tB[q] = B2[q];
        #pragma unroll 1
        for (int c = 0; c < NI / 4; c++) {
            float4 x = __ldg(r0 + c);
            acc1<6>(tB, x.x, s_wn + (4 * c + 0) * PW + 28);
            acc1<6>(tB, x.y, s_wn + (4 * c + 1) * PW + 28);
            acc1<6>(tB, x.z, s_wn + (4 * c + 2) * PW + 28);
            acc1<6>(tB, x.w, s_wn + (4 * c + 3) * PW + 28);
        }
        #pragma unroll
        for (int k = 0; k < 12; k++) {
            float2 p = up2(tB[k]);
            acc1<13>(o, relu_f(p.x), s_wu + (28 + 2 * k) * PW);
            acc1<13>(o, relu_f(p.y), s_wu + (29 + 2 * k) * PW);
        }
    }
    {
        const float4* A = reinterpret_cast<const float4*>(g_acc + (size_t)v * PW);
        #pragma unroll 1
        for (int c = 0; c < 13; c++) {
            float4 a = __ldg(A + c);
            acc1<13>(o, a.x, s_wu + (50 + 4 * c + 0) * PW);
            acc1<13>(o, a.y, s_wu + (50 + 4 * c + 1) * PW);
            acc1<13>(o, a.z, s_wu + (50 + 4 * c + 2) * PW);
            acc1<13>(o, a.w, s_wu + (50 + 4 * c + 3) * PW);
        }
    }

    float* O = out_node + (size_t)v * H;
    #pragma unroll
    for (int q = 0; q < 25; q++) {
        float2 p = up2(o[q]);
        reinterpret_cast<float2*>(O)[q] = make_float2(relu_f(p.x), relu_f(p.y));
    }
}

// ---------------------------------------------------------------------------
extern "C" void kernel_launch(void* const* d_in, const int* in_sizes, int n_in,
                              void* d_out, int out_size) {
    const float* nf    = (const float*)d_in[0];
    const float* ef    = (const float*)d_in[1];
    const int*   srcp  = (const int*)d_in[2];
    const int*   dstp  = (const int*)d_in[3];
    const float* w_n2n = (const float*)d_in[4];  const float* b_n2n = (const float*)d_in[5];
    const float* w_e2n = (const float*)d_in[6];  const float* b_e2n = (const float*)d_in[7];
    const float* w_upn = (const float*)d_in[8];  const float* b_upn = (const float*)d_in[9];
    const float* w_l   = (const float*)d_in[10]; const float* b_l   = (const float*)d_in[11];
    const float* w_r   = (const float*)d_in[12]; const float* b_r   = (const float*)d_in[13];
    const float* w_e2e = (const float*)d_in[14]; const float* b_e2e = (const float*)d_in[15];
    const float* w_upe = (const float*)d_in[16]; const float* b_upe = (const float*)d_in[17];

    float* out_node = (float*)d_out;
    float* out_edge = out_node + (size_t)V_N * H;

    size_t sm_lr   = (size_t)(2 * NI * PW + 2 * PW) * 4;
    size_t sm_edge = (size_t)SM_EDGE_F * 4;   // 191696 bytes
    size_t sm_fin  = (size_t)(NI * PW + 102 * PW + 2 * PW) * 4;

    cudaFuncSetAttribute(k_node_lr,    cudaFuncAttributeMaxDynamicSharedMemorySize, (int)sm_lr);
    cudaFuncSetAttribute(k_edge,       cudaFuncAttributeMaxDynamicSharedMemorySize, (int)sm_edge);
    cudaFuncSetAttribute(k_node_final, cudaFuncAttributeMaxDynamicSharedMemorySize, (int)sm_fin);

    int nblk = (V_N + NT - 1) / NT;   // 391
    k_shift<<<1, 32>>>();   // two shims: capture (4th launch) lands on k_edge
    k_shift<<<1, 32>>>();
    k_node_lr<<<nblk, NT, sm_lr>>>(nf, w_l, b_l, w_r, b_r);
    k_edge<<<148, NTE, sm_edge>>>(ef, srcp, dstp, w_e2n, b_e2n, w_e2e, b_e2e,
                                  w_upe, b_upe, out_edge);
    k_node_final<<<nblk, NT, sm_fin>>>(nf, w_n2n, b_n2n, w_upn, b_upn, out_node);
}